// round 4
// baseline (speedup 1.0000x reference)
#include <cuda_runtime.h>
#include <cuda_bf16.h>
#include <cstdint>

#define MAX_NODES 100000
#define MAX_EDGES 1600000
#define D 128

// ---------------------------------------------------------------------------
// Scratch (__device__ globals: allocation-free rule)
// ---------------------------------------------------------------------------
__device__ __align__(16) float g_summed[(size_t)MAX_NODES * D];  // agg result
__device__ int g_count[MAX_NODES];
__device__ int g_rowptr[MAX_NODES + 1];
__device__ int g_cursor[MAX_NODES];
__device__ int g_csr_src[MAX_EDGES];
__device__ int g_src[MAX_EDGES];
__device__ int g_dst[MAX_EDGES];
__device__ int g_is64;

#define SCAN_T 256
#define SCAN_B 128
#define SCAN_PER 4   // 128*256*4 = 131072 >= 100001
__device__ int g_blocksum[SCAN_B];

// ---------------------------------------------------------------------------
// Phase -1: detect edge_index dtype (int64 vs int32), device-side.
// int64 little-endian with values < 2^31: every odd int32 word is 0.
// ---------------------------------------------------------------------------
__global__ void detect_kernel(const int* __restrict__ ei32) {
    if (threadIdx.x == 0 && blockIdx.x == 0) {
        int nz = 0;
#pragma unroll 1
        for (int i = 0; i < 64; i++) nz |= ei32[2 * i + 1];
        g_is64 = (nz == 0) ? 1 : 0;
    }
}

// Phase -0.5: normalize edge lists into int32 g_src/g_dst
__global__ void decode_kernel(const int* __restrict__ ei32, int E) {
    int e = blockIdx.x * blockDim.x + threadIdx.x;
    if (e >= E) return;
    if (g_is64) {
        // int64 layout: 2E longs; src at long index e, dst at long index E+e
        g_src[e] = ei32[2 * e];
        g_dst[e] = ei32[2 * (E + e)];
    } else {
        g_src[e] = ei32[e];
        g_dst[e] = ei32[E + e];
    }
}

// ---------------------------------------------------------------------------
// Phase 0: zero counters
// ---------------------------------------------------------------------------
__global__ void init_kernel(int N) {
    int i = blockIdx.x * blockDim.x + threadIdx.x;
    if (i < N) g_count[i] = 0;
}

// ---------------------------------------------------------------------------
// Phase 1: degree histogram over dst
// ---------------------------------------------------------------------------
__global__ void hist_kernel(int E) {
    int e = blockIdx.x * blockDim.x + threadIdx.x;
    if (e < E) atomicAdd(&g_count[g_dst[e]], 1);
}

// ---------------------------------------------------------------------------
// Phase 2: exclusive scan of g_count -> g_rowptr (3 kernels)
// ---------------------------------------------------------------------------
__global__ __launch_bounds__(SCAN_T) void scan1_kernel(int N) {
    __shared__ int sh[SCAN_T];
    int t = threadIdx.x, b = blockIdx.x;
    int base = (b * SCAN_T + t) * SCAN_PER;
    int v[SCAN_PER];
    int s = 0;
#pragma unroll
    for (int i = 0; i < SCAN_PER; i++) {
        v[i] = (base + i < N) ? g_count[base + i] : 0;
        s += v[i];
    }
    sh[t] = s;
    __syncthreads();
    for (int off = 1; off < SCAN_T; off <<= 1) {
        int xv = (t >= off) ? sh[t - off] : 0;
        __syncthreads();
        sh[t] += xv;
        __syncthreads();
    }
    int run = sh[t] - s;   // exclusive prefix within block
#pragma unroll
    for (int i = 0; i < SCAN_PER; i++) {
        if (base + i < N) g_rowptr[base + i] = run;  // in-block partial
        run += v[i];
    }
    if (t == SCAN_T - 1) g_blocksum[b] = sh[t];
}

__global__ __launch_bounds__(SCAN_B) void scan2_kernel() {
    __shared__ int sh[SCAN_B];
    int t = threadIdx.x;
    int orig = g_blocksum[t];
    sh[t] = orig;
    __syncthreads();
    for (int off = 1; off < SCAN_B; off <<= 1) {
        int xv = (t >= off) ? sh[t - off] : 0;
        __syncthreads();
        sh[t] += xv;
        __syncthreads();
    }
    g_blocksum[t] = sh[t] - orig;  // exclusive block offsets
}

__global__ __launch_bounds__(SCAN_T) void scan3_kernel(int N, int E) {
    int t = threadIdx.x, b = blockIdx.x;
    int off = g_blocksum[b];
    int base = (b * SCAN_T + t) * SCAN_PER;
#pragma unroll
    for (int i = 0; i < SCAN_PER; i++) {
        int idx = base + i;
        if (idx < N) {
            int r = g_rowptr[idx] + off;
            g_rowptr[idx] = r;
            g_cursor[idx] = r;
        }
    }
    if (b == 0 && t == 0) g_rowptr[N] = E;
}

// ---------------------------------------------------------------------------
// Phase 3: fill CSR src lists
// ---------------------------------------------------------------------------
__global__ void fill_kernel(int E) {
    int e = blockIdx.x * blockDim.x + threadIdx.x;
    if (e < E) {
        int pos = atomicAdd(&g_cursor[g_dst[e]], 1);
        g_csr_src[pos] = g_src[e];
    }
}

// ---------------------------------------------------------------------------
// Phase 4: gather-aggregate (mean). One warp per dst node; lane owns 1 float4.
// ---------------------------------------------------------------------------
__global__ __launch_bounds__(256) void agg_kernel(const float* __restrict__ x, int N) {
    int w = (blockIdx.x * blockDim.x + threadIdx.x) >> 5;
    int lane = threadIdx.x & 31;
    if (w >= N) return;
    int beg = g_rowptr[w];
    int end = g_rowptr[w + 1];
    const float4* xb = reinterpret_cast<const float4*>(x);
    float4 acc = make_float4(0.f, 0.f, 0.f, 0.f);
    int e = beg;
    for (; e + 3 < end; e += 4) {
        int s0 = g_csr_src[e];
        int s1 = g_csr_src[e + 1];
        int s2 = g_csr_src[e + 2];
        int s3 = g_csr_src[e + 3];
        float4 a = __ldg(xb + (size_t)s0 * 32 + lane);
        float4 b = __ldg(xb + (size_t)s1 * 32 + lane);
        float4 c = __ldg(xb + (size_t)s2 * 32 + lane);
        float4 d = __ldg(xb + (size_t)s3 * 32 + lane);
        acc.x += a.x + b.x + c.x + d.x;
        acc.y += a.y + b.y + c.y + d.y;
        acc.z += a.z + b.z + c.z + d.z;
        acc.w += a.w + b.w + c.w + d.w;
    }
    for (; e < end; e++) {
        int s = g_csr_src[e];
        float4 a = __ldg(xb + (size_t)s * 32 + lane);
        acc.x += a.x; acc.y += a.y; acc.z += a.z; acc.w += a.w;
    }
    float inv = 1.0f / fmaxf((float)(end - beg), 1.0f);
    acc.x *= inv; acc.y *= inv; acc.z *= inv; acc.w *= inv;
    reinterpret_cast<float4*>(g_summed)[(size_t)w * 32 + lane] = acc;
}

// ---------------------------------------------------------------------------
// Phase 5: fused dual GEMM + bias.
//   out[n][o] = sum_k agg[n][k]*W_l[o][k] + x[n][k]*W_r[o][k]  + b_l[o]
// 128x128 block tile, 256 threads, 8x8 register tile each, K chunked by 16.
// ---------------------------------------------------------------------------
#define KC 16
#define TN 128
#define PAD 4

__global__ __launch_bounds__(256) void gemm_kernel(
    const float* __restrict__ x,
    const float* __restrict__ Wl,
    const float* __restrict__ bl,
    const float* __restrict__ Wr,
    float* __restrict__ out,
    int N) {
    __shared__ __align__(16) float a_s[KC][TN + PAD];
    __shared__ __align__(16) float x_s[KC][TN + PAD];
    __shared__ __align__(16) float wl_s[KC][TN + PAD];
    __shared__ __align__(16) float wr_s[KC][TN + PAD];

    const int tid  = threadIdx.x;
    const int colg = tid & 15;   // 16 groups of 8 output columns
    const int ng   = tid >> 4;   // 16 groups of 8 nodes
    const int node0 = blockIdx.x * TN;

    float acc[8][8];
#pragma unroll
    for (int i = 0; i < 8; i++)
#pragma unroll
        for (int j = 0; j < 8; j++) acc[i][j] = 0.f;

    for (int kc = 0; kc < D; kc += KC) {
        __syncthreads();
#pragma unroll
        for (int r = 0; r < 2; r++) {
            int idx = tid + r * 256;       // 0..511
            int row = idx >> 2;            // 0..127
            int kq  = (idx & 3) * 4;       // 0,4,8,12

            float4 xv4 = make_float4(0.f, 0.f, 0.f, 0.f);
            float4 av4 = make_float4(0.f, 0.f, 0.f, 0.f);
            int gn = node0 + row;
            if (gn < N) {
                xv4 = __ldg(reinterpret_cast<const float4*>(x + (size_t)gn * D + kc + kq));
                av4 = *reinterpret_cast<const float4*>(g_summed + (size_t)gn * D + kc + kq);
            }
            x_s[kq + 0][row] = xv4.x; x_s[kq + 1][row] = xv4.y;
            x_s[kq + 2][row] = xv4.z; x_s[kq + 3][row] = xv4.w;
            a_s[kq + 0][row] = av4.x; a_s[kq + 1][row] = av4.y;
            a_s[kq + 2][row] = av4.z; a_s[kq + 3][row] = av4.w;

            float4 wl4 = __ldg(reinterpret_cast<const float4*>(Wl + row * D + kc + kq));
            float4 wr4 = __ldg(reinterpret_cast<const float4*>(Wr + row * D + kc + kq));
            wl_s[kq + 0][row] = wl4.x; wl_s[kq + 1][row] = wl4.y;
            wl_s[kq + 2][row] = wl4.z; wl_s[kq + 3][row] = wl4.w;
            wr_s[kq + 0][row] = wr4.x; wr_s[kq + 1][row] = wr4.y;
            wr_s[kq + 2][row] = wr4.z; wr_s[kq + 3][row] = wr4.w;
        }
        __syncthreads();

#pragma unroll
        for (int k = 0; k < KC; k++) {
            float av[8], xv[8], wl[8], wr[8];
            *reinterpret_cast<float4*>(&av[0]) = *reinterpret_cast<const float4*>(&a_s[k][ng * 8]);
            *reinterpret_cast<float4*>(&av[4]) = *reinterpret_cast<const float4*>(&a_s[k][ng * 8 + 4]);
            *reinterpret_cast<float4*>(&xv[0]) = *reinterpret_cast<const float4*>(&x_s[k][ng * 8]);
            *reinterpret_cast<float4*>(&xv[4]) = *reinterpret_cast<const float4*>(&x_s[k][ng * 8 + 4]);
            *reinterpret_cast<float4*>(&wl[0]) = *reinterpret_cast<const float4*>(&wl_s[k][colg * 8]);
            *reinterpret_cast<float4*>(&wl[4]) = *reinterpret_cast<const float4*>(&wl_s[k][colg * 8 + 4]);
            *reinterpret_cast<float4*>(&wr[0]) = *reinterpret_cast<const float4*>(&wr_s[k][colg * 8]);
            *reinterpret_cast<float4*>(&wr[4]) = *reinterpret_cast<const float4*>(&wr_s[k][colg * 8 + 4]);
#pragma unroll
            for (int i = 0; i < 8; i++)
#pragma unroll
                for (int j = 0; j < 8; j++)
                    acc[i][j] = fmaf(av[i], wl[j], fmaf(xv[i], wr[j], acc[i][j]));
        }
    }

    float blv[8];
#pragma unroll
    for (int j = 0; j < 8; j++) blv[j] = __ldg(bl + colg * 8 + j);

#pragma unroll
    for (int i = 0; i < 8; i++) {
        int gn = node0 + ng * 8 + i;
        if (gn < N) {
            float4 o0, o1;
            o0.x = acc[i][0] + blv[0]; o0.y = acc[i][1] + blv[1];
            o0.z = acc[i][2] + blv[2]; o0.w = acc[i][3] + blv[3];
            o1.x = acc[i][4] + blv[4]; o1.y = acc[i][5] + blv[5];
            o1.z = acc[i][6] + blv[6]; o1.w = acc[i][7] + blv[7];
            float* op = out + (size_t)gn * D + colg * 8;
            *reinterpret_cast<float4*>(op)     = o0;
            *reinterpret_cast<float4*>(op + 4) = o1;
        }
    }
}

// ---------------------------------------------------------------------------
extern "C" void kernel_launch(void* const* d_in, const int* in_sizes, int n_in,
                              void* d_out, int out_size) {
    const float* x    = (const float*)d_in[0];
    const int*   ei32 = (const int*)d_in[1];
    const float* Wl   = (const float*)d_in[2];
    const float* bl   = (const float*)d_in[3];
    const float* Wr   = (const float*)d_in[4];
    float*       out  = (float*)d_out;

    int N = in_sizes[0] / D;       // 100000
    int E = in_sizes[1] / 2;       // 1600000

    detect_kernel<<<1, 32>>>(ei32);
    decode_kernel<<<(E + 255) / 256, 256>>>(ei32, E);
    init_kernel<<<(N + 255) / 256, 256>>>(N);
    hist_kernel<<<(E + 255) / 256, 256>>>(E);
    scan1_kernel<<<SCAN_B, SCAN_T>>>(N);
    scan2_kernel<<<1, SCAN_B>>>();
    scan3_kernel<<<SCAN_B, SCAN_T>>>(N, E);
    fill_kernel<<<(E + 255) / 256, 256>>>(E);
    {
        int grid = (N * 32 + 255) / 256;
        agg_kernel<<<grid, 256>>>(x, N);
    }
    gemm_kernel<<<(N + TN - 1) / TN, 256>>>(x, Wl, bl, Wr, out, N);
}

// round 6
// speedup vs baseline: 1.3562x; 1.3562x over previous
#include <cuda_runtime.h>
#include <cuda_bf16.h>
#include <mma.h>
#include <cstdint>

using namespace nvcuda;

#define MAX_NODES 100000
#define MAX_EDGES 1600000
#define D 128

// ---------------------------------------------------------------------------
// Scratch (__device__ globals: allocation-free rule)
// ---------------------------------------------------------------------------
__device__ __align__(16) float g_summed[(size_t)MAX_NODES * D];  // agg result
__device__ int g_count[MAX_NODES];
__device__ int g_rowptr[MAX_NODES + 1];
__device__ int g_cursor[MAX_NODES];
__device__ int g_csr_src[MAX_EDGES];
__device__ int g_src[MAX_EDGES];
__device__ int g_dst[MAX_EDGES];
__device__ int g_is64;
// W_cat = [W_l ; W_r] as [128 out-cols][256 k] bf16, split hi/lo
__device__ __align__(16) unsigned short g_Whi[128 * 256];
__device__ __align__(16) unsigned short g_Wlo[128 * 256];

#define SCAN_T 256
#define SCAN_B 128
#define SCAN_PER 4   // 128*256*4 = 131072 >= 100001
__device__ int g_blocksum[SCAN_B];

// ---------------------------------------------------------------------------
// Phase -1: detect edge_index dtype (int64 vs int32)
// ---------------------------------------------------------------------------
__global__ void detect_kernel(const int* __restrict__ ei32) {
    if (threadIdx.x == 0 && blockIdx.x == 0) {
        int nz = 0;
#pragma unroll 1
        for (int i = 0; i < 64; i++) nz |= ei32[2 * i + 1];
        g_is64 = (nz == 0) ? 1 : 0;
    }
}

__global__ void init_kernel(int N) {
    int i = blockIdx.x * blockDim.x + threadIdx.x;
    if (i < N) g_count[i] = 0;
}

// Phase 0: normalize edges + degree histogram (fused)
__global__ void decode_hist_kernel(const int* __restrict__ ei32, int E) {
    int e = blockIdx.x * blockDim.x + threadIdx.x;
    if (e >= E) return;
    int s, d;
    if (g_is64) { s = ei32[2 * e]; d = ei32[2 * (E + e)]; }
    else        { s = ei32[e];     d = ei32[E + e]; }
    g_src[e] = s;
    g_dst[e] = d;
    atomicAdd(&g_count[d], 1);
}

// Phase 0b: preconvert W_cat to bf16 hi/lo, layout [o][k], k=0..255
__global__ void wconv_kernel(const float* __restrict__ Wl, const float* __restrict__ Wr) {
    int t = blockIdx.x * blockDim.x + threadIdx.x;
    if (t >= 128 * 256) return;
    int o = t >> 8, k = t & 255;
    float w = (k < 128) ? Wl[o * 128 + k] : Wr[o * 128 + (k - 128)];
    __nv_bfloat16 hi = __float2bfloat16(w);
    float rem = w - __bfloat162float(hi);
    g_Whi[t] = __bfloat16_as_ushort(hi);
    g_Wlo[t] = __bfloat16_as_ushort(__float2bfloat16(rem));
}

// ---------------------------------------------------------------------------
// Phase 2: exclusive scan of g_count -> g_rowptr (3 kernels)
// ---------------------------------------------------------------------------
__global__ __launch_bounds__(SCAN_T) void scan1_kernel(int N) {
    __shared__ int sh[SCAN_T];
    int t = threadIdx.x, b = blockIdx.x;
    int base = (b * SCAN_T + t) * SCAN_PER;
    int v[SCAN_PER];
    int s = 0;
#pragma unroll
    for (int i = 0; i < SCAN_PER; i++) {
        v[i] = (base + i < N) ? g_count[base + i] : 0;
        s += v[i];
    }
    sh[t] = s;
    __syncthreads();
    for (int off = 1; off < SCAN_T; off <<= 1) {
        int xv = (t >= off) ? sh[t - off] : 0;
        __syncthreads();
        sh[t] += xv;
        __syncthreads();
    }
    int run = sh[t] - s;
#pragma unroll
    for (int i = 0; i < SCAN_PER; i++) {
        if (base + i < N) g_rowptr[base + i] = run;
        run += v[i];
    }
    if (t == SCAN_T - 1) g_blocksum[b] = sh[t];
}

__global__ __launch_bounds__(SCAN_B) void scan2_kernel() {
    __shared__ int sh[SCAN_B];
    int t = threadIdx.x;
    int orig = g_blocksum[t];
    sh[t] = orig;
    __syncthreads();
    for (int off = 1; off < SCAN_B; off <<= 1) {
        int xv = (t >= off) ? sh[t - off] : 0;
        __syncthreads();
        sh[t] += xv;
        __syncthreads();
    }
    g_blocksum[t] = sh[t] - orig;
}

__global__ __launch_bounds__(SCAN_T) void scan3_kernel(int N, int E) {
    int t = threadIdx.x, b = blockIdx.x;
    int off = g_blocksum[b];
    int base = (b * SCAN_T + t) * SCAN_PER;
#pragma unroll
    for (int i = 0; i < SCAN_PER; i++) {
        int idx = base + i;
        if (idx < N) {
            int r = g_rowptr[idx] + off;
            g_rowptr[idx] = r;
            g_cursor[idx] = r;
        }
    }
    if (b == 0 && t == 0) g_rowptr[N] = E;
}

// Phase 3: fill CSR src lists
__global__ void fill_kernel(int E) {
    int e = blockIdx.x * blockDim.x + threadIdx.x;
    if (e < E) {
        int pos = atomicAdd(&g_cursor[g_dst[e]], 1);
        g_csr_src[pos] = g_src[e];
    }
}

// ---------------------------------------------------------------------------
// Phase 4: gather-aggregate (mean). One warp per dst node; lane owns 1 float4.
// ---------------------------------------------------------------------------
__global__ __launch_bounds__(256) void agg_kernel(const float* __restrict__ x, int N) {
    int w = (blockIdx.x * blockDim.x + threadIdx.x) >> 5;
    int lane = threadIdx.x & 31;
    if (w >= N) return;
    int beg = g_rowptr[w];
    int end = g_rowptr[w + 1];
    const float4* xb = reinterpret_cast<const float4*>(x);
    float4 acc = make_float4(0.f, 0.f, 0.f, 0.f);
    int e = beg;
    for (; e + 3 < end; e += 4) {
        int s0 = g_csr_src[e];
        int s1 = g_csr_src[e + 1];
        int s2 = g_csr_src[e + 2];
        int s3 = g_csr_src[e + 3];
        float4 a = __ldg(xb + (size_t)s0 * 32 + lane);
        float4 b = __ldg(xb + (size_t)s1 * 32 + lane);
        float4 c = __ldg(xb + (size_t)s2 * 32 + lane);
        float4 d = __ldg(xb + (size_t)s3 * 32 + lane);
        acc.x += a.x + b.x + c.x + d.x;
        acc.y += a.y + b.y + c.y + d.y;
        acc.z += a.z + b.z + c.z + d.z;
        acc.w += a.w + b.w + c.w + d.w;
    }
    for (; e < end; e++) {
        int s = g_csr_src[e];
        float4 a = __ldg(xb + (size_t)s * 32 + lane);
        acc.x += a.x; acc.y += a.y; acc.z += a.z; acc.w += a.w;
    }
    float inv = 1.0f / fmaxf((float)(end - beg), 1.0f);
    acc.x *= inv; acc.y *= inv; acc.z *= inv; acc.w *= inv;
    reinterpret_cast<float4*>(g_summed)[(size_t)w * 32 + lane] = acc;
}

// ---------------------------------------------------------------------------
// Phase 5: WMMA bf16 GEMM with 3-term compensated split.
//   out[128n x 128o] = Acat[128 x 256] * Wcat^T + bias
//   D += Ahi*Whi + Ahi*Wlo + Alo*Whi  (fp32 accumulators, bias preloaded)
// CTA: 128 rows x 128 cols, 256 threads = 8 warps, warp tile 32x64 (2x4 frags).
// K staged in chunks of 16; smem stride 24 halves (48B: 16B-aligned rows,
// conflict-free ldmatrix bank pattern).
// ---------------------------------------------------------------------------
#define ASTR 24

__global__ __launch_bounds__(256, 2) void gemm_wmma_kernel(
    const float* __restrict__ x,
    const float* __restrict__ bl,
    float* __restrict__ out,
    int N) {
    __shared__ __align__(16) __nv_bfloat16 ahi_s[128 * ASTR];
    __shared__ __align__(16) __nv_bfloat16 alo_s[128 * ASTR];
    __shared__ __align__(16) __nv_bfloat16 whi_s[128 * ASTR];
    __shared__ __align__(16) __nv_bfloat16 wlo_s[128 * ASTR];
    __shared__ __align__(16) float bias_s[16 * 128];

    const int tid = threadIdx.x;
    const int wid = tid >> 5;
    const int node0 = blockIdx.x * 128;
    const int wr = (wid & 3) * 32;   // warp row offset
    const int wc = (wid >> 2) * 64;  // warp col offset

    // bias tile: 16 identical rows of bl[0..127]
    {
        float bv = __ldg(bl + (tid & 127));
        int r0 = tid >> 7;  // 0 or 1
#pragma unroll
        for (int r = 0; r < 16; r += 2)
            bias_s[(r + r0) * 128 + (tid & 127)] = bv;
    }
    __syncthreads();

    wmma::fragment<wmma::accumulator, 16, 16, 16, float> acc[2][4];
#pragma unroll
    for (int i = 0; i < 2; i++)
#pragma unroll
        for (int j = 0; j < 4; j++)
            wmma::load_matrix_sync(acc[i][j], &bias_s[wc + j * 16], 128, wmma::mem_row_major);

    const int row = tid >> 1;        // 0..127 (node row AND W out-col)
    const int seg = (tid & 1) * 8;   // half-row segment of 8 halves
    const int gn  = node0 + row;
    const bool va = (gn < N);

#pragma unroll 1
    for (int c = 0; c < 16; c++) {
        __syncthreads();
        // ---- stage A chunk (fp32 -> bf16 hi/lo): k = c*16 + seg + 0..7 ----
        {
            const float* ap = (c < 8)
                ? (g_summed + (size_t)gn * D + c * 16 + seg)
                : (x        + (size_t)gn * D + (c - 8) * 16 + seg);
            float4 f0 = va ? __ldg(reinterpret_cast<const float4*>(ap))     : make_float4(0.f, 0.f, 0.f, 0.f);
            float4 f1 = va ? __ldg(reinterpret_cast<const float4*>(ap) + 1) : make_float4(0.f, 0.f, 0.f, 0.f);
            float f[8] = {f0.x, f0.y, f0.z, f0.w, f1.x, f1.y, f1.z, f1.w};
            uint32_t hiw[2], low[2];
#pragma unroll
            for (int q = 0; q < 2; q++) {
                uint32_t h = 0, l = 0;
#pragma unroll
                for (int i = 0; i < 2; i++) {
                    float v0 = f[q * 4 + 2 * i], v1 = f[q * 4 + 2 * i + 1];
                    __nv_bfloat16 h0 = __float2bfloat16(v0);
                    __nv_bfloat16 h1 = __float2bfloat16(v1);
                    float r0 = v0 - __bfloat162float(h0);
                    float r1 = v1 - __bfloat162float(h1);
                    uint32_t hw = (uint32_t)__bfloat16_as_ushort(h0) | ((uint32_t)__bfloat16_as_ushort(h1) << 16);
                    uint32_t lw = (uint32_t)__bfloat16_as_ushort(__float2bfloat16(r0)) |
                                  ((uint32_t)__bfloat16_as_ushort(__float2bfloat16(r1)) << 16);
                    if (i == 0) { h = hw; l = lw; }
                    else {
                        // pack as two u32s per uint2 half
                        hiw[q] = 0; low[q] = 0; // placeholder overwritten below
                        hiw[q] = h; low[q] = l; // keep first
                        h = hw; l = lw;
                    }
                }
                // write pair (built sequentially)
                uint2 hv, lv;
                {
                    // rebuild cleanly: convert 4 floats
                    float v0 = f[q * 4 + 0], v1 = f[q * 4 + 1], v2 = f[q * 4 + 2], v3 = f[q * 4 + 3];
                    __nv_bfloat16 a0 = __float2bfloat16(v0), a1 = __float2bfloat16(v1);
                    __nv_bfloat16 a2 = __float2bfloat16(v2), a3 = __float2bfloat16(v3);
                    hv.x = (uint32_t)__bfloat16_as_ushort(a0) | ((uint32_t)__bfloat16_as_ushort(a1) << 16);
                    hv.y = (uint32_t)__bfloat16_as_ushort(a2) | ((uint32_t)__bfloat16_as_ushort(a3) << 16);
                    lv.x = (uint32_t)__bfloat16_as_ushort(__float2bfloat16(v0 - __bfloat162float(a0))) |
                           ((uint32_t)__bfloat16_as_ushort(__float2bfloat16(v1 - __bfloat162float(a1))) << 16);
                    lv.y = (uint32_t)__bfloat16_as_ushort(__float2bfloat16(v2 - __bfloat162float(a2))) |
                           ((uint32_t)__bfloat16_as_ushort(__float2bfloat16(v3 - __bfloat162float(a3))) << 16);
                }
                *reinterpret_cast<uint2*>(&ahi_s[row * ASTR + seg + q * 4]) = hv;
                *reinterpret_cast<uint2*>(&alo_s[row * ASTR + seg + q * 4]) = lv;
            }
        }
        // ---- stage W chunk (bf16 preconverted): row = out col ----
        {
            const uint4 wh = __ldg(reinterpret_cast<const uint4*>(g_Whi + row * 256 + c * 16 + seg));
            const uint4 wl = __ldg(reinterpret_cast<const uint4*>(g_Wlo + row * 256 + c * 16 + seg));
            *reinterpret_cast<uint4*>(&whi_s[row * ASTR + seg]) = wh;
            *reinterpret_cast<uint4*>(&wlo_s[row * ASTR + seg]) = wl;
        }
        __syncthreads();

        // ---- compute: 2 row frags x 4 col frags x 3 passes ----
        wmma::fragment<wmma::matrix_a, 16, 16, 16, __nv_bfloat16, wmma::row_major> ah[2], al[2];
        wmma::fragment<wmma::matrix_b, 16, 16, 16, __nv_bfloat16, wmma::col_major> bh[4], blf[4];
#pragma unroll
        for (int i = 0; i < 2; i++) {
            wmma::load_matrix_sync(ah[i], &ahi_s[(wr + i * 16) * ASTR], ASTR);
            wmma::load_matrix_sync(al[i], &alo_s[(wr + i * 16) * ASTR], ASTR);
        }
#pragma unroll
        for (int j = 0; j < 4; j++) {
            wmma::load_matrix_sync(bh[j],  &whi_s[(wc + j * 16) * ASTR], ASTR);
            wmma::load_matrix_sync(blf[j], &wlo_s[(wc + j * 16) * ASTR], ASTR);
        }
#pragma unroll
        for (int i = 0; i < 2; i++)
#pragma unroll
            for (int j = 0; j < 4; j++) {
                wmma::mma_sync(acc[i][j], ah[i], bh[j],  acc[i][j]);
                wmma::mma_sync(acc[i][j], ah[i], blf[j], acc[i][j]);
                wmma::mma_sync(acc[i][j], al[i], bh[j],  acc[i][j]);
            }
    }

    // ---- epilogue: direct fragment stores (bias already in acc) ----
#pragma unroll
    for (int i = 0; i < 2; i++) {
        int r0 = node0 + wr + i * 16;
        if (r0 < N) {  // N % 16 == 0 -> frag fully valid
#pragma unroll
            for (int j = 0; j < 4; j++)
                wmma::store_matrix_sync(out + (size_t)r0 * D + wc + j * 16, acc[i][j], D, wmma::mem_row_major);
        }
    }
}

// ---------------------------------------------------------------------------
extern "C" void kernel_launch(void* const* d_in, const int* in_sizes, int n_in,
                              void* d_out, int out_size) {
    const float* x    = (const float*)d_in[0];
    const int*   ei32 = (const int*)d_in[1];
    const float* Wl   = (const float*)d_in[2];
    const float* bl   = (const float*)d_in[3];
    const float* Wr   = (const float*)d_in[4];
    float*       out  = (float*)d_out;

    int N = in_sizes[0] / D;       // 100000
    int E = in_sizes[1] / 2;       // 1600000

    detect_kernel<<<1, 32>>>(ei32);
    init_kernel<<<(N + 255) / 256, 256>>>(N);
    decode_hist_kernel<<<(E + 255) / 256, 256>>>(ei32, E);
    wconv_kernel<<<(128 * 256 + 255) / 256, 256>>>(Wl, Wr);
    scan1_kernel<<<SCAN_B, SCAN_T>>>(N);
    scan2_kernel<<<1, SCAN_B>>>();
    scan3_kernel<<<SCAN_B, SCAN_T>>>(N, E);
    fill_kernel<<<(E + 255) / 256, 256>>>(E);
    agg_kernel<<<(N * 32 + 255) / 256, 256>>>(x, N);
    gemm_wmma_kernel<<<(N + 127) / 128, 256>>>(x, bl, out, N);
}